// round 7
// baseline (speedup 1.0000x reference)
#include <cuda_runtime.h>
#include <cstdint>

// ---------------------------------------------------------------------------
// y = (xq @ W) * (x_scale*Y_SCALE) + bias
//   x: [2048, 4096] f32, W: [4096, 11008] delivered as INT32 (harness promotes
//   int8 -> int32; rel_err 1.1178 = sqrt(1.25) fingerprint proved this),
//   bias: [11008] f32, out f32.
// NOTE: harness PTX target is plain sm_103 (no 'a') -> tcgen05 unavailable.
// Tensor path: mma.sync.m16n8k32 s8 (IMMA) + ldmatrix, baseline PTX.
// ---------------------------------------------------------------------------
#define M_DIM 2048
#define K_DIM 4096
#define N_DIM 11008
#define Y_SCALE 0.0123f

__device__ int8_t g_xq[M_DIM * K_DIM];          // 8 MB quantized activations
__device__ int8_t g_Wt[(size_t)N_DIM * K_DIM];  // 45 MB W transposed to [N,K] s8
__device__ unsigned int g_absmax_bits;

// ---------------------------------------------------------------------------
// PTX helpers (baseline PTX, sm_80+)
// ---------------------------------------------------------------------------
static __device__ __forceinline__ uint32_t smem_u32(const void* p) {
    return (uint32_t)__cvta_generic_to_shared(p);
}
static __device__ __forceinline__ void cp_async16(uint32_t smem_addr, const void* gptr) {
    asm volatile("cp.async.cg.shared.global [%0], [%1], 16;"
                 :: "r"(smem_addr), "l"(gptr) : "memory");
}
static __device__ __forceinline__ void cp_commit() {
    asm volatile("cp.async.commit_group;" ::: "memory");
}
template <int N>
static __device__ __forceinline__ void cp_wait() {
    asm volatile("cp.async.wait_group %0;" :: "n"(N) : "memory");
}
static __device__ __forceinline__ void ldsm_x4(int& r0, int& r1, int& r2, int& r3,
                                               uint32_t addr) {
    asm volatile("ldmatrix.sync.aligned.m8n8.x4.shared.b16 {%0,%1,%2,%3}, [%4];"
                 : "=r"(r0), "=r"(r1), "=r"(r2), "=r"(r3) : "r"(addr));
}
static __device__ __forceinline__ void ldsm_x2(int& r0, int& r1, uint32_t addr) {
    asm volatile("ldmatrix.sync.aligned.m8n8.x2.shared.b16 {%0,%1}, [%2];"
                 : "=r"(r0), "=r"(r1) : "r"(addr));
}
// mma.sync m16n8k32 row.col s32.s8.s8.s32
static __device__ __forceinline__ void mma_s8(
    int& c0, int& c1, int& c2, int& c3,
    int a0, int a1, int a2, int a3, int b0, int b1)
{
    asm volatile(
        "mma.sync.aligned.m16n8k32.row.col.s32.s8.s8.s32 "
        "{%0,%1,%2,%3}, {%4,%5,%6,%7}, {%8,%9}, {%0,%1,%2,%3};"
        : "+r"(c0), "+r"(c1), "+r"(c2), "+r"(c3)
        : "r"(a0), "r"(a1), "r"(a2), "r"(a3), "r"(b0), "r"(b1));
}

// ---------------------------------------------------------------------------
// Kernel 0: reset absmax scratch (graph replays must be deterministic)
// ---------------------------------------------------------------------------
__global__ void init_kernel() { g_absmax_bits = 0u; }

// ---------------------------------------------------------------------------
// Kernel 1: global max(|x|) reduction
// ---------------------------------------------------------------------------
__global__ void absmax_kernel(const float* __restrict__ x) {
    const float4* x4 = reinterpret_cast<const float4*>(x);
    const int n4 = (M_DIM * K_DIM) / 4;
    int tid = blockIdx.x * blockDim.x + threadIdx.x;
    int stride = gridDim.x * blockDim.x;
    float m = 0.0f;
    for (int i = tid; i < n4; i += stride) {
        float4 v = x4[i];
        m = fmaxf(m, fmaxf(fmaxf(fabsf(v.x), fabsf(v.y)), fmaxf(fabsf(v.z), fabsf(v.w))));
    }
    #pragma unroll
    for (int o = 16; o > 0; o >>= 1) m = fmaxf(m, __shfl_xor_sync(0xFFFFFFFFu, m, o));
    __shared__ float wmax[8];
    if ((threadIdx.x & 31) == 0) wmax[threadIdx.x >> 5] = m;
    __syncthreads();
    if (threadIdx.x < 32) {
        float mm = (threadIdx.x < (blockDim.x >> 5)) ? wmax[threadIdx.x] : 0.0f;
        #pragma unroll
        for (int o = 4; o > 0; o >>= 1) mm = fmaxf(mm, __shfl_xor_sync(0xFFFFFFFFu, mm, o));
        if (threadIdx.x == 0) atomicMax(&g_absmax_bits, __float_as_uint(mm));
    }
}

// ---------------------------------------------------------------------------
// Kernel 2: quantize x -> int8 with EXACT reference arithmetic:
//   xs = absmax/128 (exact);  q = clip(rint(x / xs), -128, 127)
// ---------------------------------------------------------------------------
__global__ void quantize_kernel(const float* __restrict__ x) {
    int i = blockIdx.x * blockDim.x + threadIdx.x;   // one float4 per thread
    float xs = __uint_as_float(g_absmax_bits) * (1.0f / 128.0f);
    float4 v = reinterpret_cast<const float4*>(x)[i];
    float a = fminf(fmaxf(rintf(v.x / xs), -128.0f), 127.0f);
    float b = fminf(fmaxf(rintf(v.y / xs), -128.0f), 127.0f);
    float c = fminf(fmaxf(rintf(v.z / xs), -128.0f), 127.0f);
    float d = fminf(fmaxf(rintf(v.w / xs), -128.0f), 127.0f);
    char4 q;
    q.x = (signed char)(int)a; q.y = (signed char)(int)b;
    q.z = (signed char)(int)c; q.w = (signed char)(int)d;
    reinterpret_cast<char4*>(g_xq)[i] = q;
}

// ---------------------------------------------------------------------------
// Kernel 3: W int32 [K,N] -> Wt int8 [N,K], 128x128 tiles via SMEM.
// Reads int32 elements (harness dtype), narrows to s8, transposes.
// ---------------------------------------------------------------------------
__global__ __launch_bounds__(256) void transpose_kernel(const int* __restrict__ W32) {
    __shared__ signed char tb[128][132];     // byte tile, padded
    const int bn = blockIdx.x * 128;         // n0
    const int bk = blockIdx.y * 128;         // k0
    const int t = threadIdx.x;
    // load: tb[k_local][n_local] = (s8)W32[bk+k][bn+n]; 4 int32 per thread/iter
    #pragma unroll
    for (int i = 0; i < 16; i++) {
        int f = t + 256 * i;
        int row = f >> 5;          // k_local 0..127
        int u = f & 31;            // group of 4 n-values
        int4 v = *reinterpret_cast<const int4*>(W32 + (size_t)(bk + row) * N_DIM + bn + 4 * u);
        tb[row][4 * u + 0] = (signed char)v.x;
        tb[row][4 * u + 1] = (signed char)v.y;
        tb[row][4 * u + 2] = (signed char)v.z;
        tb[row][4 * u + 3] = (signed char)v.w;
    }
    __syncthreads();
    // store: Wt[bn+n][bk+k] = tb[k][n]
    #pragma unroll
    for (int i = 0; i < 16; i++) {
        int f = t + 256 * i;
        int nl = f >> 5;           // n_local 0..127
        int u = f & 31;            // k segment (4 bytes)
        int k0l = 4 * u;
        char4 v;
        v.x = tb[k0l + 0][nl];
        v.y = tb[k0l + 1][nl];
        v.z = tb[k0l + 2][nl];
        v.w = tb[k0l + 3][nl];
        *reinterpret_cast<char4*>(g_Wt + (size_t)(bn + nl) * K_DIM + bk + k0l) = v;
    }
}

// ---------------------------------------------------------------------------
// Kernel 4: int8 IMMA GEMM. CTA tile 128x128, 256 threads (2x4 warps,
// warp tile 64x32), K staged in chunks of 64 via cp.async, 4 stages.
// Fragments loaded with ldmatrix (hardware-defined layout).
// PITCH 80: conflict-free ldmatrix row pattern (banks row*20 mod 32 disjoint).
// ---------------------------------------------------------------------------
static constexpr int NSTAGES = 4;
static constexpr int PITCH = 80;                        // 64B data + 16B pad
static constexpr uint32_t A_SZ = 128 * PITCH;           // 10240
static constexpr uint32_t STAGE = 2 * A_SZ;             // 20480
static constexpr uint32_t SMEM_TOTAL = NSTAGES * STAGE; // 81920

static __device__ __forceinline__ void load_stage(uint32_t sb, int s,
                                                  int chunk, int m0, int n0, int tid) {
    const int k0 = chunk * 64;
    const uint32_t base = sb + (uint32_t)s * STAGE;
    // A: 128 rows x 4 segs of 16B = 512 segs; 256 threads -> 2 each
    #pragma unroll
    for (int j = 0; j < 2; j++) {
        int f = tid + 256 * j;
        int row = f >> 2, seg = f & 3;
        cp_async16(base + (uint32_t)(row * PITCH + seg * 16),
                   g_xq + (size_t)(m0 + row) * K_DIM + k0 + seg * 16);
    }
    // B: 128 rows x 4 segs
    #pragma unroll
    for (int j = 0; j < 2; j++) {
        int f = tid + 256 * j;
        int row = f >> 2, seg = f & 3;
        cp_async16(base + A_SZ + (uint32_t)(row * PITCH + seg * 16),
                   g_Wt + (size_t)(n0 + row) * K_DIM + k0 + seg * 16);
    }
}

__global__ __launch_bounds__(256, 2) void gemm_kernel(const float* __restrict__ bias,
                                                      float* __restrict__ out) {
    extern __shared__ char smem[];
    const uint32_t sb = smem_u32(smem);
    const int tid = threadIdx.x;
    const int wid = tid >> 5;
    const int lid = tid & 31;
    const int g = lid >> 2;          // group 0..7
    const int q = lid & 3;           // quad  0..3
    const int warp_row = (wid >> 2) * 64;   // 0 or 64
    const int warp_col = (wid & 3) * 32;    // 0,32,64,96
    const int m0 = blockIdx.y * 128;
    const int n0 = blockIdx.x * 128;

    // ldmatrix lane-address offsets (within a tile, bytes)
    const uint32_t aoff = (uint32_t)((lid & 15) * PITCH + (lid >> 4) * 16);
    const uint32_t boff = (uint32_t)((lid & 7) * PITCH + ((lid >> 3) & 1) * 16);

    int acc[4][4][4];                // [mtile][ntile][c0..c3]
    #pragma unroll
    for (int t = 0; t < 4; t++)
        #pragma unroll
        for (int u = 0; u < 4; u++)
            #pragma unroll
            for (int r = 0; r < 4; r++) acc[t][u][r] = 0;

    const int KCHUNKS = K_DIM / 64;  // 64

    // prologue: stages 0..2
    #pragma unroll
    for (int c = 0; c < NSTAGES - 1; c++) {
        load_stage(sb, c, c, m0, n0, tid);
        cp_commit();
    }

    for (int c = 0; c < KCHUNKS; c++) {
        const int s = c & (NSTAGES - 1);
        cp_wait<NSTAGES - 2>();
        __syncthreads();

        // ALWAYS prefetch + commit (wrap chunk index at the tail) so the
        // cp.async group accounting stays uniform.
        const int nc = c + NSTAGES - 1;
        const int ncw = (nc < KCHUNKS) ? nc : (nc - KCHUNKS);
        load_stage(sb, nc & (NSTAGES - 1), ncw, m0, n0, tid);
        cp_commit();

        const uint32_t sA = sb + (uint32_t)s * STAGE;
        const uint32_t sB = sA + A_SZ;
        #pragma unroll
        for (int ks = 0; ks < 64; ks += 32) {
            int a[4][4], bb[4][2];
            #pragma unroll
            for (int t = 0; t < 4; t++)
                ldsm_x4(a[t][0], a[t][1], a[t][2], a[t][3],
                        sA + (uint32_t)((warp_row + t * 16) * PITCH + ks) + aoff);
            #pragma unroll
            for (int u = 0; u < 4; u++)
                ldsm_x2(bb[u][0], bb[u][1],
                        sB + (uint32_t)((warp_col + u * 8) * PITCH + ks) + boff);
            #pragma unroll
            for (int u = 0; u < 4; u++)
                #pragma unroll
                for (int t = 0; t < 4; t++)
                    mma_s8(acc[t][u][0], acc[t][u][1], acc[t][u][2], acc[t][u][3],
                           a[t][0], a[t][1], a[t][2], a[t][3], bb[u][0], bb[u][1]);
        }
    }

    // epilogue: y = s32 * alpha + bias (alpha = absmax/128 * Y_SCALE)
    const float alpha = __uint_as_float(g_absmax_bits) * (1.0f / 128.0f) * Y_SCALE;
    #pragma unroll
    for (int t = 0; t < 4; t++) {
        const int r0 = m0 + warp_row + t * 16 + g;
        #pragma unroll
        for (int u = 0; u < 4; u++) {
            const int col = n0 + warp_col + u * 8 + q * 2;
            const float2 bv = *reinterpret_cast<const float2*>(bias + col);
            float2 o0, o1;
            o0.x = (float)acc[t][u][0] * alpha + bv.x;
            o0.y = (float)acc[t][u][1] * alpha + bv.y;
            o1.x = (float)acc[t][u][2] * alpha + bv.x;
            o1.y = (float)acc[t][u][3] * alpha + bv.y;
            *reinterpret_cast<float2*>(out + (size_t)r0 * N_DIM + col) = o0;
            *reinterpret_cast<float2*>(out + (size_t)(r0 + 8) * N_DIM + col) = o1;
        }
    }
}

// ---------------------------------------------------------------------------
// Launcher — inputs identified by element count (robust to metadata order):
//   x: 2048*4096 = 8388608 f32 | W: 4096*11008 = 45088768 INT32 | bias: 11008 f32
// ---------------------------------------------------------------------------
extern "C" void kernel_launch(void* const* d_in, const int* in_sizes, int n_in,
                              void* d_out, int out_size) {
    (void)out_size;
    const float* x    = nullptr;
    const int*   W32  = nullptr;
    const float* bias = nullptr;
    for (int i = 0; i < n_in; i++) {
        if (in_sizes[i] == M_DIM * K_DIM)       x    = (const float*)d_in[i];
        else if (in_sizes[i] == N_DIM)          bias = (const float*)d_in[i];
        else                                    W32  = (const int*)d_in[i];
    }
    float* out = (float*)d_out;

    init_kernel<<<1, 1>>>();
    absmax_kernel<<<2048, 256>>>(x);
    quantize_kernel<<<(M_DIM * K_DIM / 4) / 256, 256>>>(x);
    transpose_kernel<<<dim3(N_DIM / 128, K_DIM / 128), 256>>>(W32);

    cudaFuncSetAttribute(gemm_kernel, cudaFuncAttributeMaxDynamicSharedMemorySize,
                         (int)SMEM_TOTAL);
    gemm_kernel<<<dim3(N_DIM / 128, M_DIM / 128), 256, SMEM_TOTAL>>>(bias, out);
}

// round 8
// speedup vs baseline: 1.9652x; 1.9652x over previous
#include <cuda_runtime.h>
#include <cuda_bf16.h>
#include <cstdint>

// ---------------------------------------------------------------------------
// y = (xq @ W) * (x_scale*Y_SCALE) + bias
//   x: [2048,4096] f32, W: [4096,11008] int32 (harness-promoted int8),
//   bias: [11008] f32, out f32.
// Round-7 result: int8 mma.sync path = 253 MAC/cyc/SM == dp4a rate -> legacy
// INT8 tensor path is dead on sm_103. Legacy FP path (HMMA) is real HW
// (pitfalls.md: "fallback HMMA"). int8 values are exact in bf16; products
// exact in f32 -> switch GEMM operands to bf16, mma.m16n8k16.f32.bf16.
// Byte-level SMEM layout / ldmatrix addressing identical to the validated
// int8 kernel; only the MMA opcode, chunk count, and f32 accum change.
// ---------------------------------------------------------------------------
#define M_DIM 2048
#define K_DIM 4096
#define N_DIM 11008
#define Y_SCALE 0.0123f

__device__ __nv_bfloat16 g_xa[(size_t)M_DIM * K_DIM];   // 16 MB quantized acts (bf16)
__device__ __nv_bfloat16 g_Wtb[(size_t)N_DIM * K_DIM];  // 90 MB W^T (bf16, [N,K])
__device__ unsigned int g_absmax_bits;

// ---------------------------------------------------------------------------
// PTX helpers (baseline PTX, sm_80+)
// ---------------------------------------------------------------------------
static __device__ __forceinline__ uint32_t smem_u32(const void* p) {
    return (uint32_t)__cvta_generic_to_shared(p);
}
static __device__ __forceinline__ void cp_async16(uint32_t smem_addr, const void* gptr) {
    asm volatile("cp.async.cg.shared.global [%0], [%1], 16;"
                 :: "r"(smem_addr), "l"(gptr) : "memory");
}
static __device__ __forceinline__ void cp_commit() {
    asm volatile("cp.async.commit_group;" ::: "memory");
}
template <int N>
static __device__ __forceinline__ void cp_wait() {
    asm volatile("cp.async.wait_group %0;" :: "n"(N) : "memory");
}
static __device__ __forceinline__ void ldsm_x4(int& r0, int& r1, int& r2, int& r3,
                                               uint32_t addr) {
    asm volatile("ldmatrix.sync.aligned.m8n8.x4.shared.b16 {%0,%1,%2,%3}, [%4];"
                 : "=r"(r0), "=r"(r1), "=r"(r2), "=r"(r3) : "r"(addr));
}
static __device__ __forceinline__ void ldsm_x2(int& r0, int& r1, uint32_t addr) {
    asm volatile("ldmatrix.sync.aligned.m8n8.x2.shared.b16 {%0,%1}, [%2];"
                 : "=r"(r0), "=r"(r1) : "r"(addr));
}
// mma.sync m16n8k16 row.col f32.bf16.bf16.f32 (HMMA fallback path on sm_103a)
static __device__ __forceinline__ void mma_bf16(
    float& c0, float& c1, float& c2, float& c3,
    int a0, int a1, int a2, int a3, int b0, int b1)
{
    asm volatile(
        "mma.sync.aligned.m16n8k16.row.col.f32.bf16.bf16.f32 "
        "{%0,%1,%2,%3}, {%4,%5,%6,%7}, {%8,%9}, {%0,%1,%2,%3};"
        : "+f"(c0), "+f"(c1), "+f"(c2), "+f"(c3)
        : "r"(a0), "r"(a1), "r"(a2), "r"(a3), "r"(b0), "r"(b1));
}

static __device__ __forceinline__ uint32_t bf16bits(__nv_bfloat16 h) {
    return (uint32_t)__bfloat16_as_ushort(h);
}

// ---------------------------------------------------------------------------
// Kernel 0: reset absmax scratch (graph replays must be deterministic)
// ---------------------------------------------------------------------------
__global__ void init_kernel() { g_absmax_bits = 0u; }

// ---------------------------------------------------------------------------
// Kernel 1: global max(|x|) reduction
// ---------------------------------------------------------------------------
__global__ void absmax_kernel(const float* __restrict__ x) {
    const float4* x4 = reinterpret_cast<const float4*>(x);
    const int n4 = (M_DIM * K_DIM) / 4;
    int tid = blockIdx.x * blockDim.x + threadIdx.x;
    int stride = gridDim.x * blockDim.x;
    float m = 0.0f;
    for (int i = tid; i < n4; i += stride) {
        float4 v = x4[i];
        m = fmaxf(m, fmaxf(fmaxf(fabsf(v.x), fabsf(v.y)), fmaxf(fabsf(v.z), fabsf(v.w))));
    }
    #pragma unroll
    for (int o = 16; o > 0; o >>= 1) m = fmaxf(m, __shfl_xor_sync(0xFFFFFFFFu, m, o));
    __shared__ float wmax[8];
    if ((threadIdx.x & 31) == 0) wmax[threadIdx.x >> 5] = m;
    __syncthreads();
    if (threadIdx.x < 32) {
        float mm = (threadIdx.x < (blockDim.x >> 5)) ? wmax[threadIdx.x] : 0.0f;
        #pragma unroll
        for (int o = 4; o > 0; o >>= 1) mm = fmaxf(mm, __shfl_xor_sync(0xFFFFFFFFu, mm, o));
        if (threadIdx.x == 0) atomicMax(&g_absmax_bits, __float_as_uint(mm));
    }
}

// ---------------------------------------------------------------------------
// Kernel 2: quantize x -> bf16-encoded int8 values (exact reference math):
//   xs = absmax/128;  q = clip(rint(x / xs), -128, 127)  (exact in bf16)
// ---------------------------------------------------------------------------
__global__ void quantize_kernel(const float* __restrict__ x) {
    int i = blockIdx.x * blockDim.x + threadIdx.x;   // one float4 per thread
    float xs = __uint_as_float(g_absmax_bits) * (1.0f / 128.0f);
    float4 v = reinterpret_cast<const float4*>(x)[i];
    float a = fminf(fmaxf(rintf(v.x / xs), -128.0f), 127.0f);
    float b = fminf(fmaxf(rintf(v.y / xs), -128.0f), 127.0f);
    float c = fminf(fmaxf(rintf(v.z / xs), -128.0f), 127.0f);
    float d = fminf(fmaxf(rintf(v.w / xs), -128.0f), 127.0f);
    uint32_t lo = bf16bits(__float2bfloat16_rn(a)) | (bf16bits(__float2bfloat16_rn(b)) << 16);
    uint32_t hi = bf16bits(__float2bfloat16_rn(c)) | (bf16bits(__float2bfloat16_rn(d)) << 16);
    uint2 pk; pk.x = lo; pk.y = hi;
    reinterpret_cast<uint2*>(g_xa)[i] = pk;         // 4 bf16 = 8 B, aligned
}

// ---------------------------------------------------------------------------
// Kernel 3: W int32 [K,N] -> Wtb bf16 [N,K], 128x128 tiles via SMEM
// ---------------------------------------------------------------------------
__global__ __launch_bounds__(256) void transpose_kernel(const int* __restrict__ W32) {
    __shared__ __nv_bfloat16 tb[128][132];   // bf16 tile, padded (33 KB)
    const int bn = blockIdx.x * 128;         // n0
    const int bk = blockIdx.y * 128;         // k0
    const int t = threadIdx.x;
    // load: tb[k_local][n_local] = bf16(W32[bk+k][bn+n]); 4 int32/thread/iter
    #pragma unroll
    for (int i = 0; i < 16; i++) {
        int f = t + 256 * i;
        int row = f >> 5;          // k_local 0..127
        int u = f & 31;            // group of 4 n-values
        int4 v = *reinterpret_cast<const int4*>(W32 + (size_t)(bk + row) * N_DIM + bn + 4 * u);
        tb[row][4 * u + 0] = __float2bfloat16_rn((float)v.x);
        tb[row][4 * u + 1] = __float2bfloat16_rn((float)v.y);
        tb[row][4 * u + 2] = __float2bfloat16_rn((float)v.z);
        tb[row][4 * u + 3] = __float2bfloat16_rn((float)v.w);
    }
    __syncthreads();
    // store: Wtb[bn+n][bk+k] = tb[k][n]  (4 bf16 = 8 B per store)
    #pragma unroll
    for (int i = 0; i < 16; i++) {
        int f = t + 256 * i;
        int nl = f >> 5;           // n_local 0..127
        int u = f & 31;            // k segment (4 elements)
        int k0l = 4 * u;
        uint32_t w0 = bf16bits(tb[k0l + 0][nl]) | (bf16bits(tb[k0l + 1][nl]) << 16);
        uint32_t w1 = bf16bits(tb[k0l + 2][nl]) | (bf16bits(tb[k0l + 3][nl]) << 16);
        uint2 pk; pk.x = w0; pk.y = w1;
        *reinterpret_cast<uint2*>(&g_Wtb[(size_t)(bn + nl) * K_DIM + bk + k0l]) = pk;
    }
}

// ---------------------------------------------------------------------------
// Kernel 4: bf16 HMMA GEMM. CTA tile 128x128, 256 threads (2x4 warps,
// warp tile 64x32), K staged in chunks of 32 bf16 (64 B) via cp.async,
// 4 stages. Fragments via ldmatrix. Byte layout identical to the validated
// int8 kernel (PITCH 80, conflict-free).
// ---------------------------------------------------------------------------
static constexpr int NSTAGES = 4;
static constexpr int PITCH = 80;                        // 64B data + 16B pad
static constexpr uint32_t A_SZ = 128 * PITCH;           // 10240
static constexpr uint32_t STAGE = 2 * A_SZ;             // 20480
static constexpr uint32_t SMEM_TOTAL = NSTAGES * STAGE; // 81920

static __device__ __forceinline__ void load_stage(uint32_t sb, int s,
                                                  int chunk, int m0, int n0, int tid) {
    const int k0 = chunk * 32;                          // 32 bf16 elements = 64 B
    const uint32_t base = sb + (uint32_t)s * STAGE;
    // A: 128 rows x 4 segs of 16B (8 bf16) = 512 segs; 256 threads -> 2 each
    #pragma unroll
    for (int j = 0; j < 2; j++) {
        int f = tid + 256 * j;
        int row = f >> 2, seg = f & 3;
        cp_async16(base + (uint32_t)(row * PITCH + seg * 16),
                   g_xa + (size_t)(m0 + row) * K_DIM + k0 + seg * 8);
    }
    // B: 128 rows x 4 segs
    #pragma unroll
    for (int j = 0; j < 2; j++) {
        int f = tid + 256 * j;
        int row = f >> 2, seg = f & 3;
        cp_async16(base + A_SZ + (uint32_t)(row * PITCH + seg * 16),
                   g_Wtb + (size_t)(n0 + row) * K_DIM + k0 + seg * 8);
    }
}

__global__ __launch_bounds__(256, 2) void gemm_kernel(const float* __restrict__ bias,
                                                      float* __restrict__ out) {
    extern __shared__ char smem[];
    const uint32_t sb = smem_u32(smem);
    const int tid = threadIdx.x;
    const int wid = tid >> 5;
    const int lid = tid & 31;
    const int g = lid >> 2;          // group 0..7
    const int q = lid & 3;           // quad  0..3
    const int warp_row = (wid >> 2) * 64;   // 0 or 64
    const int warp_col = (wid & 3) * 32;    // 0,32,64,96
    const int m0 = blockIdx.y * 128;
    const int n0 = blockIdx.x * 128;

    // ldmatrix lane-address offsets (within a tile, bytes) — same as int8 ver.
    const uint32_t aoff = (uint32_t)((lid & 15) * PITCH + (lid >> 4) * 16);
    const uint32_t boff = (uint32_t)((lid & 7) * PITCH + ((lid >> 3) & 1) * 16);

    float acc[4][4][4];              // [mtile][ntile][c0..c3]
    #pragma unroll
    for (int t = 0; t < 4; t++)
        #pragma unroll
        for (int u = 0; u < 4; u++)
            #pragma unroll
            for (int r = 0; r < 4; r++) acc[t][u][r] = 0.0f;

    const int KCHUNKS = K_DIM / 32;  // 128

    // prologue: stages 0..2
    #pragma unroll
    for (int c = 0; c < NSTAGES - 1; c++) {
        load_stage(sb, c, c, m0, n0, tid);
        cp_commit();
    }

    for (int c = 0; c < KCHUNKS; c++) {
        const int s = c & (NSTAGES - 1);
        cp_wait<NSTAGES - 2>();
        __syncthreads();

        // ALWAYS prefetch + commit (wrap chunk index at the tail) so the
        // cp.async group accounting stays uniform.
        const int nc = c + NSTAGES - 1;
        const int ncw = (nc < KCHUNKS) ? nc : (nc - KCHUNKS);
        load_stage(sb, nc & (NSTAGES - 1), ncw, m0, n0, tid);
        cp_commit();

        const uint32_t sA = sb + (uint32_t)s * STAGE;
        const uint32_t sB = sA + A_SZ;
        #pragma unroll
        for (int ks = 0; ks < 64; ks += 32) {     // two k16 steps (32 B each)
            int a[4][4], bb[4][2];
            #pragma unroll
            for (int t = 0; t < 4; t++)
                ldsm_x4(a[t][0], a[t][1], a[t][2], a[t][3],
                        sA + (uint32_t)((warp_row + t * 16) * PITCH + ks) + aoff);
            #pragma unroll
            for (int u = 0; u < 4; u++)
                ldsm_x2(bb[u][0], bb[u][1],
                        sB + (uint32_t)((warp_col + u * 8) * PITCH + ks) + boff);
            #pragma unroll
            for (int u = 0; u < 4; u++)
                #pragma unroll
                for (int t = 0; t < 4; t++)
                    mma_bf16(acc[t][u][0], acc[t][u][1], acc[t][u][2], acc[t][u][3],
                             a[t][0], a[t][1], a[t][2], a[t][3], bb[u][0], bb[u][1]);
        }
    }

    // epilogue: y = c * alpha + bias (alpha = absmax/128 * Y_SCALE)
    const float alpha = __uint_as_float(g_absmax_bits) * (1.0f / 128.0f) * Y_SCALE;
    #pragma unroll
    for (int t = 0; t < 4; t++) {
        const int r0 = m0 + warp_row + t * 16 + g;
        #pragma unroll
        for (int u = 0; u < 4; u++) {
            const int col = n0 + warp_col + u * 8 + q * 2;
            const float2 bv = *reinterpret_cast<const float2*>(bias + col);
            float2 o0, o1;
            o0.x = acc[t][u][0] * alpha + bv.x;
            o0.y = acc[t][u][1] * alpha + bv.y;
            o1.x = acc[t][u][2] * alpha + bv.x;
            o1.y = acc[t][u][3] * alpha + bv.y;
            *reinterpret_cast<float2*>(out + (size_t)r0 * N_DIM + col) = o0;
            *reinterpret_cast<float2*>(out + (size_t)(r0 + 8) * N_DIM + col) = o1;
        }
    }
}

// ---------------------------------------------------------------------------
// Launcher — inputs identified by element count (robust to metadata order):
//   x: 2048*4096 = 8388608 f32 | W: 4096*11008 = 45088768 INT32 | bias: 11008 f32
// ---------------------------------------------------------------------------
extern "C" void kernel_launch(void* const* d_in, const int* in_sizes, int n_in,
                              void* d_out, int out_size) {
    (void)out_size;
    const float* x    = nullptr;
    const int*   W32  = nullptr;
    const float* bias = nullptr;
    for (int i = 0; i < n_in; i++) {
        if (in_sizes[i] == M_DIM * K_DIM)       x    = (const float*)d_in[i];
        else if (in_sizes[i] == N_DIM)          bias = (const float*)d_in[i];
        else                                    W32  = (const int*)d_in[i];
    }
    float* out = (float*)d_out;

    init_kernel<<<1, 1>>>();
    absmax_kernel<<<2048, 256>>>(x);
    quantize_kernel<<<(M_DIM * K_DIM / 4) / 256, 256>>>(x);
    transpose_kernel<<<dim3(N_DIM / 128, K_DIM / 128), 256>>>(W32);

    cudaFuncSetAttribute(gemm_kernel, cudaFuncAttributeMaxDynamicSharedMemorySize,
                         (int)SMEM_TOTAL);
    gemm_kernel<<<dim3(N_DIM / 128, M_DIM / 128), 256, SMEM_TOTAL>>>(bias, out);
}

// round 9
// speedup vs baseline: 2.3163x; 1.1787x over previous
#include <cuda_runtime.h>
#include <cuda_bf16.h>
#include <cstdint>

// ---------------------------------------------------------------------------
// y = (xq @ W) * (x_scale*Y_SCALE) + bias
//   x: [2048,4096] f32, W: [4096,11008] int32 (harness-promoted int8),
//   bias: [11008] f32, out f32.
// GEMM: legacy HMMA mma.m16n8k16.f32.bf16 (int8 values exact in bf16).
// B kept in [K,N] bf16 (convert only, no transpose) and loaded with
// ldmatrix.x2.trans. 4 launches so ncu's capture window hits the GEMM.
// ---------------------------------------------------------------------------
#define M_DIM 2048
#define K_DIM 4096
#define N_DIM 11008
#define Y_SCALE 0.0123f

__device__ __nv_bfloat16 g_xa[(size_t)M_DIM * K_DIM];   // 16 MB bf16 acts
__device__ __nv_bfloat16 g_Wb[(size_t)K_DIM * N_DIM];   // 90 MB bf16 W [K,N]
__device__ float g_part[2048];                          // absmax partials
__device__ float g_absmax;

// ---------------------------------------------------------------------------
// PTX helpers (baseline PTX, sm_80+)
// ---------------------------------------------------------------------------
static __device__ __forceinline__ uint32_t smem_u32(const void* p) {
    return (uint32_t)__cvta_generic_to_shared(p);
}
static __device__ __forceinline__ void cp_async16(uint32_t smem_addr, const void* gptr) {
    asm volatile("cp.async.cg.shared.global [%0], [%1], 16;"
                 :: "r"(smem_addr), "l"(gptr) : "memory");
}
static __device__ __forceinline__ void cp_commit() {
    asm volatile("cp.async.commit_group;" ::: "memory");
}
template <int N>
static __device__ __forceinline__ void cp_wait() {
    asm volatile("cp.async.wait_group %0;" :: "n"(N) : "memory");
}
static __device__ __forceinline__ void ldsm_x4(int& r0, int& r1, int& r2, int& r3,
                                               uint32_t addr) {
    asm volatile("ldmatrix.sync.aligned.m8n8.x4.shared.b16 {%0,%1,%2,%3}, [%4];"
                 : "=r"(r0), "=r"(r1), "=r"(r2), "=r"(r3) : "r"(addr));
}
static __device__ __forceinline__ void ldsm_x2t(int& r0, int& r1, uint32_t addr) {
    asm volatile("ldmatrix.sync.aligned.m8n8.x2.trans.shared.b16 {%0,%1}, [%2];"
                 : "=r"(r0), "=r"(r1) : "r"(addr));
}
// mma.sync m16n8k16 row.col f32.bf16.bf16.f32
static __device__ __forceinline__ void mma_bf16(
    float& c0, float& c1, float& c2, float& c3,
    int a0, int a1, int a2, int a3, int b0, int b1)
{
    asm volatile(
        "mma.sync.aligned.m16n8k16.row.col.f32.bf16.bf16.f32 "
        "{%0,%1,%2,%3}, {%4,%5,%6,%7}, {%8,%9}, {%0,%1,%2,%3};"
        : "+f"(c0), "+f"(c1), "+f"(c2), "+f"(c3)
        : "r"(a0), "r"(a1), "r"(a2), "r"(a3), "r"(b0), "r"(b1));
}
static __device__ __forceinline__ uint32_t bf16bits(__nv_bfloat16 h) {
    return (uint32_t)__bfloat16_as_ushort(h);
}

// ---------------------------------------------------------------------------
// Kernel 1: per-block |x| max -> g_part[2048]  (overwrite: deterministic)
// ---------------------------------------------------------------------------
__global__ void absmax_part_kernel(const float* __restrict__ x) {
    const float4* x4 = reinterpret_cast<const float4*>(x);
    const int n4 = (M_DIM * K_DIM) / 4;
    int tid = blockIdx.x * blockDim.x + threadIdx.x;
    int stride = gridDim.x * blockDim.x;
    float m = 0.0f;
    for (int i = tid; i < n4; i += stride) {
        float4 v = x4[i];
        m = fmaxf(m, fmaxf(fmaxf(fabsf(v.x), fabsf(v.y)), fmaxf(fabsf(v.z), fabsf(v.w))));
    }
    #pragma unroll
    for (int o = 16; o > 0; o >>= 1) m = fmaxf(m, __shfl_xor_sync(0xFFFFFFFFu, m, o));
    __shared__ float wmax[8];
    if ((threadIdx.x & 31) == 0) wmax[threadIdx.x >> 5] = m;
    __syncthreads();
    if (threadIdx.x < 32) {
        float mm = (threadIdx.x < 8) ? wmax[threadIdx.x] : 0.0f;
        #pragma unroll
        for (int o = 4; o > 0; o >>= 1) mm = fmaxf(mm, __shfl_xor_sync(0xFFFFFFFFu, mm, o));
        if (threadIdx.x == 0) g_part[blockIdx.x] = mm;
    }
}

// ---------------------------------------------------------------------------
// Kernel 2: reduce 2048 partials -> g_absmax (overwrite: deterministic)
// ---------------------------------------------------------------------------
__global__ void absmax_reduce_kernel() {
    __shared__ float sm[32];
    int t = threadIdx.x;                         // 1024 threads
    float m = fmaxf(g_part[t], g_part[t + 1024]);
    #pragma unroll
    for (int o = 16; o > 0; o >>= 1) m = fmaxf(m, __shfl_xor_sync(0xFFFFFFFFu, m, o));
    if ((t & 31) == 0) sm[t >> 5] = m;
    __syncthreads();
    if (t < 32) {
        float mm = sm[t];
        #pragma unroll
        for (int o = 16; o > 0; o >>= 1) mm = fmaxf(mm, __shfl_xor_sync(0xFFFFFFFFu, mm, o));
        if (t == 0) g_absmax = mm;
    }
}

// ---------------------------------------------------------------------------
// Kernel 3 (fused): quantize x -> bf16 int8-values AND convert W int32->bf16.
//   xs = absmax/128;  q = clip(rint(x/xs), -128, 127)    (exact in bf16)
// Thread i: converts W4[i] (4 int32 -> 4 bf16); if i < NX4 also quants x4[i].
// ---------------------------------------------------------------------------
#define NX4 (M_DIM * K_DIM / 4)                 // 2097152
#define NW4 ((size_t)K_DIM * N_DIM / 4)         // 11272192
__global__ void quant_convert_kernel(const float* __restrict__ x,
                                     const int* __restrict__ W32) {
    size_t i = (size_t)blockIdx.x * blockDim.x + threadIdx.x;
    // --- W convert: 4 int32 -> 4 bf16 ---
    int4 w = *reinterpret_cast<const int4*>(W32 + 4 * i);
    uint32_t w0 = bf16bits(__float2bfloat16_rn((float)w.x)) |
                  (bf16bits(__float2bfloat16_rn((float)w.y)) << 16);
    uint32_t w1 = bf16bits(__float2bfloat16_rn((float)w.z)) |
                  (bf16bits(__float2bfloat16_rn((float)w.w)) << 16);
    uint2 wp; wp.x = w0; wp.y = w1;
    reinterpret_cast<uint2*>(g_Wb)[i] = wp;
    // --- x quantize ---
    if (i < NX4) {
        float xs = g_absmax * (1.0f / 128.0f);
        float4 v = reinterpret_cast<const float4*>(x)[i];
        float a = fminf(fmaxf(rintf(v.x / xs), -128.0f), 127.0f);
        float b = fminf(fmaxf(rintf(v.y / xs), -128.0f), 127.0f);
        float c = fminf(fmaxf(rintf(v.z / xs), -128.0f), 127.0f);
        float d = fminf(fmaxf(rintf(v.w / xs), -128.0f), 127.0f);
        uint32_t lo = bf16bits(__float2bfloat16_rn(a)) | (bf16bits(__float2bfloat16_rn(b)) << 16);
        uint32_t hi = bf16bits(__float2bfloat16_rn(c)) | (bf16bits(__float2bfloat16_rn(d)) << 16);
        uint2 pk; pk.x = lo; pk.y = hi;
        reinterpret_cast<uint2*>(g_xa)[i] = pk;
    }
}

// ---------------------------------------------------------------------------
// Kernel 4: bf16 HMMA GEMM. CTA 128x128, 256 thr (2x4 warps, warp 64x32).
// K chunks of 64 elements (128 B), 3 stages. A [m][k] rows PITCH_A=144;
// B [k][n] rows (64 x 256 B) PITCH_B=272, fragments via ldmatrix.x2.trans.
// Both pitches === 16 mod 128 -> conflict-free ldmatrix.
// ---------------------------------------------------------------------------
static constexpr int NSTAGES = 3;
static constexpr int PITCH_A = 144;                     // 128B data + 16B pad
static constexpr int PITCH_B = 272;                     // 256B data + 16B pad
static constexpr uint32_t A_SZ = 128 * PITCH_A;         // 18432
static constexpr uint32_t B_SZ = 64 * PITCH_B;          // 17408
static constexpr uint32_t STAGE = A_SZ + B_SZ;          // 35840
static constexpr uint32_t SMEM_TOTAL = NSTAGES * STAGE; // 107520

static __device__ __forceinline__ void load_stage(uint32_t sb, int s,
                                                  int chunk, int m0, int n0, int tid) {
    const int k0 = chunk * 64;                          // element index in K
    const uint32_t abase = sb + (uint32_t)s * STAGE;
    const uint32_t bbase = abase + A_SZ;
    // A: 128 rows x 8 segs of 16B (8 bf16) = 1024; 256 thr -> 4 each
    #pragma unroll
    for (int j = 0; j < 4; j++) {
        int f = tid + 256 * j;
        int row = f >> 3, seg = f & 7;
        cp_async16(abase + (uint32_t)(row * PITCH_A + seg * 16),
                   g_xa + (size_t)(m0 + row) * K_DIM + k0 + seg * 8);
    }
    // B: 64 rows x 16 segs of 16B = 1024; rows are K, 128 n-cols contiguous
    #pragma unroll
    for (int j = 0; j < 4; j++) {
        int f = tid + 256 * j;
        int row = f >> 4, seg = f & 15;
        cp_async16(bbase + (uint32_t)(row * PITCH_B + seg * 16),
                   g_Wb + (size_t)(k0 + row) * N_DIM + n0 + seg * 8);
    }
}

__global__ __launch_bounds__(256, 2) void gemm_kernel(const float* __restrict__ bias,
                                                      float* __restrict__ out) {
    extern __shared__ char smem[];
    const uint32_t sb = smem_u32(smem);
    const int tid = threadIdx.x;
    const int wid = tid >> 5;
    const int lid = tid & 31;
    const int g = lid >> 2;          // group 0..7
    const int q = lid & 3;           // quad  0..3
    const int warp_row = (wid >> 2) * 64;   // 0 or 64
    const int warp_col = (wid & 3) * 32;    // 0,32,64,96
    const int m0 = blockIdx.y * 128;
    const int n0 = blockIdx.x * 128;

    // ldmatrix lane offsets
    const uint32_t aoff = (uint32_t)((lid & 15) * PITCH_A + (lid >> 4) * 16);
    const uint32_t brow = (uint32_t)((lid & 15) * PITCH_B);

    float acc[4][4][4];
    #pragma unroll
    for (int t = 0; t < 4; t++)
        #pragma unroll
        for (int u = 0; u < 4; u++)
            #pragma unroll
            for (int r = 0; r < 4; r++) acc[t][u][r] = 0.0f;

    const int KCHUNKS = K_DIM / 64;  // 64

    // prologue: stages 0..1
    #pragma unroll
    for (int c = 0; c < NSTAGES - 1; c++) {
        load_stage(sb, c, c, m0, n0, tid);
        cp_commit();
    }

    for (int c = 0; c < KCHUNKS; c++) {
        const int s = c % NSTAGES;
        cp_wait<NSTAGES - 2>();
        __syncthreads();

        // always prefetch + commit (wrap tail) for uniform group accounting
        const int nc = c + NSTAGES - 1;
        const int ncw = (nc < KCHUNKS) ? nc : (nc - KCHUNKS);
        load_stage(sb, nc % NSTAGES, ncw, m0, n0, tid);
        cp_commit();

        const uint32_t sA = sb + (uint32_t)s * STAGE;
        const uint32_t sB = sA + A_SZ;
        #pragma unroll
        for (int kk = 0; kk < 64; kk += 16) {    // four k16 steps
            int a[4][4], bb[4][2];
            #pragma unroll
            for (int t = 0; t < 4; t++)
                ldsm_x4(a[t][0], a[t][1], a[t][2], a[t][3],
                        sA + (uint32_t)((warp_row + t * 16) * PITCH_A + kk * 2) + aoff);
            #pragma unroll
            for (int u = 0; u < 4; u++)
                ldsm_x2t(bb[u][0], bb[u][1],
                         sB + (uint32_t)(kk * PITCH_B + (warp_col + u * 8) * 2) + brow);
            #pragma unroll
            for (int u = 0; u < 4; u++)
                #pragma unroll
                for (int t = 0; t < 4; t++)
                    mma_bf16(acc[t][u][0], acc[t][u][1], acc[t][u][2], acc[t][u][3],
                             a[t][0], a[t][1], a[t][2], a[t][3], bb[u][0], bb[u][1]);
        }
    }

    // epilogue: y = c * alpha + bias (alpha = absmax/128 * Y_SCALE)
    const float alpha = g_absmax * (1.0f / 128.0f) * Y_SCALE;
    #pragma unroll
    for (int t = 0; t < 4; t++) {
        const int r0 = m0 + warp_row + t * 16 + g;
        #pragma unroll
        for (int u = 0; u < 4; u++) {
            const int col = n0 + warp_col + u * 8 + q * 2;
            const float2 bv = *reinterpret_cast<const float2*>(bias + col);
            float2 o0, o1;
            o0.x = acc[t][u][0] * alpha + bv.x;
            o0.y = acc[t][u][1] * alpha + bv.y;
            o1.x = acc[t][u][2] * alpha + bv.x;
            o1.y = acc[t][u][3] * alpha + bv.y;
            *reinterpret_cast<float2*>(out + (size_t)r0 * N_DIM + col) = o0;
            *reinterpret_cast<float2*>(out + (size_t)(r0 + 8) * N_DIM + col) = o1;
        }
    }
}

// ---------------------------------------------------------------------------
// Launcher — inputs identified by element count:
//   x: 8388608 f32 | W: 45088768 int32 | bias: 11008 f32
// 4 launches total; GEMM is launch #4 (for the ncu capture window).
// ---------------------------------------------------------------------------
extern "C" void kernel_launch(void* const* d_in, const int* in_sizes, int n_in,
                              void* d_out, int out_size) {
    (void)out_size;
    const float* x    = nullptr;
    const int*   W32  = nullptr;
    const float* bias = nullptr;
    for (int i = 0; i < n_in; i++) {
        if (in_sizes[i] == M_DIM * K_DIM)       x    = (const float*)d_in[i];
        else if (in_sizes[i] == N_DIM)          bias = (const float*)d_in[i];
        else                                    W32  = (const int*)d_in[i];
    }
    float* out = (float*)d_out;

    absmax_part_kernel<<<2048, 256>>>(x);
    absmax_reduce_kernel<<<1, 1024>>>();
    quant_convert_kernel<<<(unsigned)(NW4 / 256), 256>>>(x, W32);

    cudaFuncSetAttribute(gemm_kernel, cudaFuncAttributeMaxDynamicSharedMemorySize,
                         (int)SMEM_TOTAL);
    gemm_kernel<<<dim3(N_DIM / 128, M_DIM / 128), 256, SMEM_TOTAL>>>(bias, out);
}

// round 10
// speedup vs baseline: 2.3823x; 1.0285x over previous
#include <cuda_runtime.h>
#include <cuda_bf16.h>
#include <cstdint>

// ---------------------------------------------------------------------------
// y = (xq @ W) * (x_scale*Y_SCALE) + bias
//   x: [2048,4096] f32, W: [4096,11008] int32 (harness-promoted int8),
//   bias: [11008] f32, out f32.
// GEMM: legacy HMMA mma.m16n8k16.f32.bf16 (rt~8/SMSP confirmed by R9 ncu).
// R9 showed smem crossbar co-saturated with tensor (10.9 MAC/smem-byte).
// This round: warp tile 64x64, CTA 128x256, 8 warps -> 16+ MAC/byte,
// tensor-bound. B in [K,N] bf16 via ldmatrix.x2.trans (validated layout).
// ---------------------------------------------------------------------------
#define M_DIM 2048
#define K_DIM 4096
#define N_DIM 11008
#define Y_SCALE 0.0123f

__device__ __nv_bfloat16 g_xa[(size_t)M_DIM * K_DIM];   // 16 MB bf16 acts
__device__ __nv_bfloat16 g_Wb[(size_t)K_DIM * N_DIM];   // 90 MB bf16 W [K,N]
__device__ float g_part[2048];                          // absmax partials
__device__ float g_absmax;

// ---------------------------------------------------------------------------
// PTX helpers (baseline PTX, sm_80+)
// ---------------------------------------------------------------------------
static __device__ __forceinline__ uint32_t smem_u32(const void* p) {
    return (uint32_t)__cvta_generic_to_shared(p);
}
static __device__ __forceinline__ void cp_async16(uint32_t smem_addr, const void* gptr) {
    asm volatile("cp.async.cg.shared.global [%0], [%1], 16;"
                 :: "r"(smem_addr), "l"(gptr) : "memory");
}
static __device__ __forceinline__ void cp_commit() {
    asm volatile("cp.async.commit_group;" ::: "memory");
}
template <int N>
static __device__ __forceinline__ void cp_wait() {
    asm volatile("cp.async.wait_group %0;" :: "n"(N) : "memory");
}
static __device__ __forceinline__ void ldsm_x4(int& r0, int& r1, int& r2, int& r3,
                                               uint32_t addr) {
    asm volatile("ldmatrix.sync.aligned.m8n8.x4.shared.b16 {%0,%1,%2,%3}, [%4];"
                 : "=r"(r0), "=r"(r1), "=r"(r2), "=r"(r3) : "r"(addr));
}
static __device__ __forceinline__ void ldsm_x2t(int& r0, int& r1, uint32_t addr) {
    asm volatile("ldmatrix.sync.aligned.m8n8.x2.trans.shared.b16 {%0,%1}, [%2];"
                 : "=r"(r0), "=r"(r1) : "r"(addr));
}
// mma.sync m16n8k16 row.col f32.bf16.bf16.f32
static __device__ __forceinline__ void mma_bf16(
    float& c0, float& c1, float& c2, float& c3,
    int a0, int a1, int a2, int a3, int b0, int b1)
{
    asm volatile(
        "mma.sync.aligned.m16n8k16.row.col.f32.bf16.bf16.f32 "
        "{%0,%1,%2,%3}, {%4,%5,%6,%7}, {%8,%9}, {%0,%1,%2,%3};"
        : "+f"(c0), "+f"(c1), "+f"(c2), "+f"(c3)
        : "r"(a0), "r"(a1), "r"(a2), "r"(a3), "r"(b0), "r"(b1));
}
static __device__ __forceinline__ uint32_t bf16bits(__nv_bfloat16 h) {
    return (uint32_t)__bfloat16_as_ushort(h);
}

// ---------------------------------------------------------------------------
// Kernel 1: per-block |x| max -> g_part[2048]  (overwrite: deterministic)
// ---------------------------------------------------------------------------
__global__ void absmax_part_kernel(const float* __restrict__ x) {
    const float4* x4 = reinterpret_cast<const float4*>(x);
    const int n4 = (M_DIM * K_DIM) / 4;
    int tid = blockIdx.x * blockDim.x + threadIdx.x;
    int stride = gridDim.x * blockDim.x;
    float m = 0.0f;
    for (int i = tid; i < n4; i += stride) {
        float4 v = x4[i];
        m = fmaxf(m, fmaxf(fmaxf(fabsf(v.x), fabsf(v.y)), fmaxf(fabsf(v.z), fabsf(v.w))));
    }
    #pragma unroll
    for (int o = 16; o > 0; o >>= 1) m = fmaxf(m, __shfl_xor_sync(0xFFFFFFFFu, m, o));
    __shared__ float wmax[8];
    if ((threadIdx.x & 31) == 0) wmax[threadIdx.x >> 5] = m;
    __syncthreads();
    if (threadIdx.x < 32) {
        float mm = (threadIdx.x < 8) ? wmax[threadIdx.x] : 0.0f;
        #pragma unroll
        for (int o = 4; o > 0; o >>= 1) mm = fmaxf(mm, __shfl_xor_sync(0xFFFFFFFFu, mm, o));
        if (threadIdx.x == 0) g_part[blockIdx.x] = mm;
    }
}

// ---------------------------------------------------------------------------
// Kernel 2: reduce 2048 partials -> g_absmax (overwrite: deterministic)
// ---------------------------------------------------------------------------
__global__ void absmax_reduce_kernel() {
    __shared__ float sm[32];
    int t = threadIdx.x;                         // 1024 threads
    float m = fmaxf(g_part[t], g_part[t + 1024]);
    #pragma unroll
    for (int o = 16; o > 0; o >>= 1) m = fmaxf(m, __shfl_xor_sync(0xFFFFFFFFu, m, o));
    if ((t & 31) == 0) sm[t >> 5] = m;
    __syncthreads();
    if (t < 32) {
        float mm = sm[t];
        #pragma unroll
        for (int o = 16; o > 0; o >>= 1) mm = fmaxf(mm, __shfl_xor_sync(0xFFFFFFFFu, mm, o));
        if (t == 0) g_absmax = mm;
    }
}

// ---------------------------------------------------------------------------
// Kernel 3 (fused): quantize x -> bf16 int8-values AND convert W int32->bf16.
// ---------------------------------------------------------------------------
#define NX4 (M_DIM * K_DIM / 4)                 // 2097152
#define NW4 ((size_t)K_DIM * N_DIM / 4)         // 11272192
__global__ void quant_convert_kernel(const float* __restrict__ x,
                                     const int* __restrict__ W32) {
    size_t i = (size_t)blockIdx.x * blockDim.x + threadIdx.x;
    int4 w = *reinterpret_cast<const int4*>(W32 + 4 * i);
    uint32_t w0 = bf16bits(__float2bfloat16_rn((float)w.x)) |
                  (bf16bits(__float2bfloat16_rn((float)w.y)) << 16);
    uint32_t w1 = bf16bits(__float2bfloat16_rn((float)w.z)) |
                  (bf16bits(__float2bfloat16_rn((float)w.w)) << 16);
    uint2 wp; wp.x = w0; wp.y = w1;
    reinterpret_cast<uint2*>(g_Wb)[i] = wp;
    if (i < NX4) {
        float xs = g_absmax * (1.0f / 128.0f);
        float4 v = reinterpret_cast<const float4*>(x)[i];
        float a = fminf(fmaxf(rintf(v.x / xs), -128.0f), 127.0f);
        float b = fminf(fmaxf(rintf(v.y / xs), -128.0f), 127.0f);
        float c = fminf(fmaxf(rintf(v.z / xs), -128.0f), 127.0f);
        float d = fminf(fmaxf(rintf(v.w / xs), -128.0f), 127.0f);
        uint32_t lo = bf16bits(__float2bfloat16_rn(a)) | (bf16bits(__float2bfloat16_rn(b)) << 16);
        uint32_t hi = bf16bits(__float2bfloat16_rn(c)) | (bf16bits(__float2bfloat16_rn(d)) << 16);
        uint2 pk; pk.x = lo; pk.y = hi;
        reinterpret_cast<uint2*>(g_xa)[i] = pk;
    }
}

// ---------------------------------------------------------------------------
// Kernel 4: bf16 HMMA GEMM. CTA 128x256, 256 thr (2x4 warps, warp 64x64).
// K chunks of 64 elems, 3 stages. A rows PITCH_A=144; B [k][n] rows of
// 512B data, PITCH_B=528. Both pitches === 16 mod 128 -> conflict-free.
// 1 CTA/SM (153KB smem, ~180 regs); 16.4 MAC/smem-byte -> tensor-bound.
// ---------------------------------------------------------------------------
static constexpr int NSTAGES = 3;
static constexpr int PITCH_A = 144;                     // 128B data + 16B pad
static constexpr int PITCH_B = 528;                     // 512B data + 16B pad
static constexpr uint32_t A_SZ = 128 * PITCH_A;         // 18432
static constexpr uint32_t B_SZ = 64 * PITCH_B;          // 33792
static constexpr uint32_t STAGE = A_SZ + B_SZ;          // 52224
static constexpr uint32_t SMEM_TOTAL = NSTAGES * STAGE; // 156672

static __device__ __forceinline__ void load_stage(uint32_t sb, int s,
                                                  int chunk, int m0, int n0, int tid) {
    const int k0 = chunk * 64;                          // element index in K
    const uint32_t abase = sb + (uint32_t)s * STAGE;
    const uint32_t bbase = abase + A_SZ;
    // A: 128 rows x 8 segs of 16B = 1024; 256 thr -> 4 each
    #pragma unroll
    for (int j = 0; j < 4; j++) {
        int f = tid + 256 * j;
        int row = f >> 3, seg = f & 7;
        cp_async16(abase + (uint32_t)(row * PITCH_A + seg * 16),
                   g_xa + (size_t)(m0 + row) * K_DIM + k0 + seg * 8);
    }
    // B: 64 rows x 32 segs of 16B (256 n-cols) = 2048; 256 thr -> 8 each
    #pragma unroll
    for (int j = 0; j < 8; j++) {
        int f = tid + 256 * j;
        int row = f >> 5, seg = f & 31;
        cp_async16(bbase + (uint32_t)(row * PITCH_B + seg * 16),
                   g_Wb + (size_t)(k0 + row) * N_DIM + n0 + seg * 8);
    }
}

__global__ __launch_bounds__(256, 1) void gemm_kernel(const float* __restrict__ bias,
                                                      float* __restrict__ out) {
    extern __shared__ char smem[];
    const uint32_t sb = smem_u32(smem);
    const int tid = threadIdx.x;
    const int wid = tid >> 5;
    const int lid = tid & 31;
    const int g = lid >> 2;          // group 0..7
    const int q = lid & 3;           // quad  0..3
    const int warp_row = (wid >> 2) * 64;   // 0 or 64
    const int warp_col = (wid & 3) * 64;    // 0,64,128,192
    const int m0 = blockIdx.y * 128;
    const int n0 = blockIdx.x * 256;

    const uint32_t aoff = (uint32_t)((lid & 15) * PITCH_A + (lid >> 4) * 16);
    const uint32_t brow = (uint32_t)((lid & 15) * PITCH_B);

    float acc[4][8][4];              // [mtile][ntile][c0..c3] = 128 regs
    #pragma unroll
    for (int t = 0; t < 4; t++)
        #pragma unroll
        for (int u = 0; u < 8; u++)
            #pragma unroll
            for (int r = 0; r < 4; r++) acc[t][u][r] = 0.0f;

    const int KCHUNKS = K_DIM / 64;  // 64

    // prologue: stages 0..1
    #pragma unroll
    for (int c = 0; c < NSTAGES - 1; c++) {
        load_stage(sb, c, c, m0, n0, tid);
        cp_commit();
    }

    for (int c = 0; c < KCHUNKS; c++) {
        const int s = c % NSTAGES;
        cp_wait<NSTAGES - 2>();
        __syncthreads();

        // always prefetch + commit (wrap tail) for uniform group accounting
        const int nc = c + NSTAGES - 1;
        const int ncw = (nc < KCHUNKS) ? nc : (nc - KCHUNKS);
        load_stage(sb, nc % NSTAGES, ncw, m0, n0, tid);
        cp_commit();

        const uint32_t sA = sb + (uint32_t)s * STAGE;
        const uint32_t sB = sA + A_SZ;
        #pragma unroll
        for (int kk = 0; kk < 64; kk += 16) {    // four k16 steps
            int a[4][4], bb[8][2];
            #pragma unroll
            for (int t = 0; t < 4; t++)
                ldsm_x4(a[t][0], a[t][1], a[t][2], a[t][3],
                        sA + (uint32_t)((warp_row + t * 16) * PITCH_A + kk * 2) + aoff);
            #pragma unroll
            for (int u = 0; u < 8; u++)
                ldsm_x2t(bb[u][0], bb[u][1],
                         sB + (uint32_t)(kk * PITCH_B + (warp_col + u * 8) * 2) + brow);
            #pragma unroll
            for (int u = 0; u < 8; u++)
                #pragma unroll
                for (int t = 0; t < 4; t++)
                    mma_bf16(acc[t][u][0], acc[t][u][1], acc[t][u][2], acc[t][u][3],
                             a[t][0], a[t][1], a[t][2], a[t][3], bb[u][0], bb[u][1]);
        }
    }

    // epilogue: y = c * alpha + bias (alpha = absmax/128 * Y_SCALE)
    const float alpha = g_absmax * (1.0f / 128.0f) * Y_SCALE;
    #pragma unroll
    for (int t = 0; t < 4; t++) {
        const int r0 = m0 + warp_row + t * 16 + g;
        #pragma unroll
        for (int u = 0; u < 8; u++) {
            const int col = n0 + warp_col + u * 8 + q * 2;
            const float2 bv = *reinterpret_cast<const float2*>(bias + col);
            float2 o0, o1;
            o0.x = acc[t][u][0] * alpha + bv.x;
            o0.y = acc[t][u][1] * alpha + bv.y;
            o1.x = acc[t][u][2] * alpha + bv.x;
            o1.y = acc[t][u][3] * alpha + bv.y;
            *reinterpret_cast<float2*>(out + (size_t)r0 * N_DIM + col) = o0;
            *reinterpret_cast<float2*>(out + (size_t)(r0 + 8) * N_DIM + col) = o1;
        }
    }
}

// ---------------------------------------------------------------------------
// Launcher — inputs identified by element count:
//   x: 8388608 f32 | W: 45088768 int32 | bias: 11008 f32
// 4 launches; GEMM is launch #4 (ncu capture window).
// ---------------------------------------------------------------------------
extern "C" void kernel_launch(void* const* d_in, const int* in_sizes, int n_in,
                              void* d_out, int out_size) {
    (void)out_size;
    const float* x    = nullptr;
    const int*   W32  = nullptr;
    const float* bias = nullptr;
    for (int i = 0; i < n_in; i++) {
        if (in_sizes[i] == M_DIM * K_DIM)       x    = (const float*)d_in[i];
        else if (in_sizes[i] == N_DIM)          bias = (const float*)d_in[i];
        else                                    W32  = (const int*)d_in[i];
    }
    float* out = (float*)d_out;

    absmax_part_kernel<<<2048, 256>>>(x);
    absmax_reduce_kernel<<<1, 1024>>>();
    quant_convert_kernel<<<(unsigned)(NW4 / 256), 256>>>(x, W32);

    cudaFuncSetAttribute(gemm_kernel, cudaFuncAttributeMaxDynamicSharedMemorySize,
                         (int)SMEM_TOTAL);
    gemm_kernel<<<dim3(N_DIM / 256, M_DIM / 128), 256, SMEM_TOTAL>>>(bias, out);
}

// round 12
// speedup vs baseline: 2.6190x; 1.0994x over previous
#include <cuda_runtime.h>
#include <cuda_bf16.h>
#include <cstdint>

// ---------------------------------------------------------------------------
// y = (xq @ W) * (x_scale*Y_SCALE) + bias
//   x: [2048,4096] f32, W: [4096,11008] int32 (promoted int8), bias f32.
// GEMM: legacy HMMA mma.m16n8k16.f32.bf16 (rt~8/SMSP). R9/R10: tensor stuck
// ~57% regardless of occupancy/smem -> per-chunk serial head is the limiter.
// R11: K-chunk 128 (half the barriers), 2 stages, cp.async issue spread
// across the kk-loop so the tensor pipe stays fed.
// ---------------------------------------------------------------------------
#define M_DIM 2048
#define K_DIM 4096
#define N_DIM 11008
#define Y_SCALE 0.0123f

__device__ __nv_bfloat16 g_xa[(size_t)M_DIM * K_DIM];   // 16 MB bf16 acts
__device__ __nv_bfloat16 g_Wb[(size_t)K_DIM * N_DIM];   // 90 MB bf16 W [K,N]
__device__ float g_part[2048];
__device__ float g_absmax;

// ---------------------------------------------------------------------------
// PTX helpers
// ---------------------------------------------------------------------------
static __device__ __forceinline__ uint32_t smem_u32(const void* p) {
    return (uint32_t)__cvta_generic_to_shared(p);
}
static __device__ __forceinline__ void cp_async16(uint32_t smem_addr, const void* gptr) {
    asm volatile("cp.async.cg.shared.global [%0], [%1], 16;"
                 :: "r"(smem_addr), "l"(gptr) : "memory");
}
static __device__ __forceinline__ void cp_commit() {
    asm volatile("cp.async.commit_group;" ::: "memory");
}
template <int N>
static __device__ __forceinline__ void cp_wait() {
    asm volatile("cp.async.wait_group %0;" :: "n"(N) : "memory");
}
static __device__ __forceinline__ void ldsm_x4(int& r0, int& r1, int& r2, int& r3,
                                               uint32_t addr) {
    asm volatile("ldmatrix.sync.aligned.m8n8.x4.shared.b16 {%0,%1,%2,%3}, [%4];"
                 : "=r"(r0), "=r"(r1), "=r"(r2), "=r"(r3) : "r"(addr));
}
static __device__ __forceinline__ void ldsm_x2t(int& r0, int& r1, uint32_t addr) {
    asm volatile("ldmatrix.sync.aligned.m8n8.x2.trans.shared.b16 {%0,%1}, [%2];"
                 : "=r"(r0), "=r"(r1) : "r"(addr));
}
static __device__ __forceinline__ void mma_bf16(
    float& c0, float& c1, float& c2, float& c3,
    int a0, int a1, int a2, int a3, int b0, int b1)
{
    asm volatile(
        "mma.sync.aligned.m16n8k16.row.col.f32.bf16.bf16.f32 "
        "{%0,%1,%2,%3}, {%4,%5,%6,%7}, {%8,%9}, {%0,%1,%2,%3};"
        : "+f"(c0), "+f"(c1), "+f"(c2), "+f"(c3)
        : "r"(a0), "r"(a1), "r"(a2), "r"(a3), "r"(b0), "r"(b1));
}
static __device__ __forceinline__ uint32_t bf16bits(__nv_bfloat16 h) {
    return (uint32_t)__bfloat16_as_ushort(h);
}

// ---------------------------------------------------------------------------
// Kernel 1: per-block |x| max -> g_part[2048]
// ---------------------------------------------------------------------------
__global__ void absmax_part_kernel(const float* __restrict__ x) {
    const float4* x4 = reinterpret_cast<const float4*>(x);
    const int n4 = (M_DIM * K_DIM) / 4;
    int tid = blockIdx.x * blockDim.x + threadIdx.x;
    int stride = gridDim.x * blockDim.x;
    float m = 0.0f;
    for (int i = tid; i < n4; i += stride) {
        float4 v = x4[i];
        m = fmaxf(m, fmaxf(fmaxf(fabsf(v.x), fabsf(v.y)), fmaxf(fabsf(v.z), fabsf(v.w))));
    }
    #pragma unroll
    for (int o = 16; o > 0; o >>= 1) m = fmaxf(m, __shfl_xor_sync(0xFFFFFFFFu, m, o));
    __shared__ float wmax[8];
    if ((threadIdx.x & 31) == 0) wmax[threadIdx.x >> 5] = m;
    __syncthreads();
    if (threadIdx.x < 32) {
        float mm = (threadIdx.x < 8) ? wmax[threadIdx.x] : 0.0f;
        #pragma unroll
        for (int o = 4; o > 0; o >>= 1) mm = fmaxf(mm, __shfl_xor_sync(0xFFFFFFFFu, mm, o));
        if (threadIdx.x == 0) g_part[blockIdx.x] = mm;
    }
}

// ---------------------------------------------------------------------------
// Kernel 2: reduce partials -> g_absmax
// ---------------------------------------------------------------------------
__global__ void absmax_reduce_kernel() {
    __shared__ float sm[32];
    int t = threadIdx.x;                         // 1024 threads
    float m = fmaxf(g_part[t], g_part[t + 1024]);
    #pragma unroll
    for (int o = 16; o > 0; o >>= 1) m = fmaxf(m, __shfl_xor_sync(0xFFFFFFFFu, m, o));
    if ((t & 31) == 0) sm[t >> 5] = m;
    __syncthreads();
    if (t < 32) {
        float mm = sm[t];
        #pragma unroll
        for (int o = 16; o > 0; o >>= 1) mm = fmaxf(mm, __shfl_xor_sync(0xFFFFFFFFu, mm, o));
        if (t == 0) g_absmax = mm;
    }
}

// ---------------------------------------------------------------------------
// Kernel 3 (fused): quantize x -> bf16; convert W int32 -> bf16.
// ---------------------------------------------------------------------------
#define NX4 (M_DIM * K_DIM / 4)
#define NW4 ((size_t)K_DIM * N_DIM / 4)
__global__ void quant_convert_kernel(const float* __restrict__ x,
                                     const int* __restrict__ W32) {
    size_t i = (size_t)blockIdx.x * blockDim.x + threadIdx.x;
    int4 w = *reinterpret_cast<const int4*>(W32 + 4 * i);
    uint32_t w0 = bf16bits(__float2bfloat16_rn((float)w.x)) |
                  (bf16bits(__float2bfloat16_rn((float)w.y)) << 16);
    uint32_t w1 = bf16bits(__float2bfloat16_rn((float)w.z)) |
                  (bf16bits(__float2bfloat16_rn((float)w.w)) << 16);
    uint2 wp; wp.x = w0; wp.y = w1;
    reinterpret_cast<uint2*>(g_Wb)[i] = wp;
    if (i < NX4) {
        float xs = g_absmax * (1.0f / 128.0f);
        float4 v = reinterpret_cast<const float4*>(x)[i];
        float a = fminf(fmaxf(rintf(v.x / xs), -128.0f), 127.0f);
        float b = fminf(fmaxf(rintf(v.y / xs), -128.0f), 127.0f);
        float c = fminf(fmaxf(rintf(v.z / xs), -128.0f), 127.0f);
        float d = fminf(fmaxf(rintf(v.w / xs), -128.0f), 127.0f);
        uint32_t lo = bf16bits(__float2bfloat16_rn(a)) | (bf16bits(__float2bfloat16_rn(b)) << 16);
        uint32_t hi = bf16bits(__float2bfloat16_rn(c)) | (bf16bits(__float2bfloat16_rn(d)) << 16);
        uint2 pk; pk.x = lo; pk.y = hi;
        reinterpret_cast<uint2*>(g_xa)[i] = pk;
    }
}

// ---------------------------------------------------------------------------
// Kernel 4: bf16 HMMA GEMM. CTA 128x256, 8 warps (2x4, warp 64x64).
// K chunk = 128 elements, 2 stages (204.8 KB smem). cp.async for the next
// chunk is issued in 8 batches interleaved with the kk-loop MMAs.
// PITCH_A=272, PITCH_B=528 (both 16B-group === 1 mod 8 -> conflict-free).
// ---------------------------------------------------------------------------
static constexpr int CHUNK_K = 128;
static constexpr int PITCH_A = 272;                     // 256B data + 16B pad
static constexpr int PITCH_B = 528;                     // 512B data + 16B pad
static constexpr uint32_t A_SZ = 128 * PITCH_A;         // 34816
static constexpr uint32_t B_SZ = 128 * PITCH_B;         // 67584
static constexpr uint32_t STAGE = A_SZ + B_SZ;          // 102400
static constexpr uint32_t SMEM_TOTAL = 2 * STAGE;       // 204800

// one batch = 1 A seg + 2 B segs per thread; 8 batches cover the whole chunk
static __device__ __forceinline__ void load_batch(uint32_t stage_base, int chunk,
                                                  int m0, int n0, int tid, int i) {
    const int k0 = chunk * CHUNK_K;
    // A: 128 rows x 16 segs of 16B = 2048 segs; batch i -> seg f = tid + 256*i
    {
        int f = tid + 256 * i;
        int row = f >> 4, seg = f & 15;
        cp_async16(stage_base + (uint32_t)(row * PITCH_A + seg * 16),
                   g_xa + (size_t)(m0 + row) * K_DIM + k0 + seg * 8);
    }
    // B: 128 rows x 32 segs of 16B = 4096 segs; batch i -> segs 2i, 2i+1
    #pragma unroll
    for (int jj = 0; jj < 2; jj++) {
        int f = tid + 256 * (2 * i + jj);
        int row = f >> 5, seg = f & 31;
        cp_async16(stage_base + A_SZ + (uint32_t)(row * PITCH_B + seg * 16),
                   g_Wb + (size_t)(k0 + row) * N_DIM + n0 + seg * 8);
    }
}

__global__ __launch_bounds__(256, 1) void gemm_kernel(const float* __restrict__ bias,
                                                      float* __restrict__ out) {
    extern __shared__ char smem[];
    const uint32_t sb = smem_u32(smem);
    const int tid = threadIdx.x;
    const int wid = tid >> 5;
    const int lid = tid & 31;
    const int g = lid >> 2;
    const int q = lid & 3;
    const int warp_row = (wid >> 2) * 64;   // 0 or 64
    const int warp_col = (wid & 3) * 64;    // 0,64,128,192
    const int m0 = blockIdx.y * 128;
    const int n0 = blockIdx.x * 256;

    const uint32_t aoff = (uint32_t)((lid & 15) * PITCH_A + (lid >> 4) * 16);
    const uint32_t brow = (uint32_t)((lid & 15) * PITCH_B);

    float acc[4][8][4];
    #pragma unroll
    for (int t = 0; t < 4; t++)
        #pragma unroll
        for (int u = 0; u < 8; u++)
            #pragma unroll
            for (int r = 0; r < 4; r++) acc[t][u][r] = 0.0f;

    const int KCHUNKS = K_DIM / CHUNK_K;   // 32

    // prologue: chunk 0 -> stage 0
    #pragma unroll
    for (int i = 0; i < 8; i++) load_batch(sb, 0, m0, n0, tid, i);
    cp_commit();

    for (int c = 0; c < KCHUNKS; c++) {
        const int s = c & 1;
        cp_wait<0>();            // own groups drained -> stage s data in smem
        __syncthreads();         // cross-thread visibility + fences stage s^1 reads

        const uint32_t sA = sb + (uint32_t)s * STAGE;
        const uint32_t sB = sA + A_SZ;
        const uint32_t nbase = sb + (uint32_t)(s ^ 1) * STAGE;
        const int nc = c + 1;
        const int ncw = (nc < KCHUNKS) ? nc : 0;   // wrap tail (harmless dummy)

        #pragma unroll
        for (int ki = 0; ki < 8; ki++) {           // 8 k16 steps
            const int kk = ki * 16;
            int a[4][4], bb[8][2];
            #pragma unroll
            for (int t = 0; t < 4; t++)
                ldsm_x4(a[t][0], a[t][1], a[t][2], a[t][3],
                        sA + (uint32_t)((warp_row + t * 16) * PITCH_A + kk * 2) + aoff);
            #pragma unroll
            for (int u = 0; u < 8; u++)
                ldsm_x2t(bb[u][0], bb[u][1],
                         sB + (uint32_t)(kk * PITCH_B + (warp_col + u * 8) * 2) + brow);
            // interleave next-chunk loads with the MMA block
            load_batch(nbase, ncw, m0, n0, tid, ki);
            #pragma unroll
            for (int u = 0; u < 8; u++)
                #pragma unroll
                for (int t = 0; t < 4; t++)
                    mma_bf16(acc[t][u][0], acc[t][u][1], acc[t][u][2], acc[t][u][3],
                             a[t][0], a[t][1], a[t][2], a[t][3], bb[u][0], bb[u][1]);
        }
        cp_commit();
    }

    // epilogue: y = c * alpha + bias
    const float alpha = g_absmax * (1.0f / 128.0f) * Y_SCALE;
    #pragma unroll
    for (int t = 0; t < 4; t++) {
        const int r0 = m0 + warp_row + t * 16 + g;
        #pragma unroll
        for (int u = 0; u < 8; u++) {
            const int col = n0 + warp_col + u * 8 + q * 2;
            const float2 bv = *reinterpret_cast<const float2*>(bias + col);
            float2 o0, o1;
            o0.x = acc[t][u][0] * alpha + bv.x;
            o0.y = acc[t][u][1] * alpha + bv.y;
            o1.x = acc[t][u][2] * alpha + bv.x;
            o1.y = acc[t][u][3] * alpha + bv.y;
            *reinterpret_cast<float2*>(out + (size_t)r0 * N_DIM + col) = o0;
            *reinterpret_cast<float2*>(out + (size_t)(r0 + 8) * N_DIM + col) = o1;
        }
    }
}

// ---------------------------------------------------------------------------
// Launcher — inputs identified by element count:
//   x: 8388608 f32 | W: 45088768 int32 | bias: 11008 f32
// ---------------------------------------------------------------------------
extern "C" void kernel_launch(void* const* d_in, const int* in_sizes, int n_in,
                              void* d_out, int out_size) {
    (void)out_size;
    const float* x    = nullptr;
    const int*   W32  = nullptr;
    const float* bias = nullptr;
    for (int i = 0; i < n_in; i++) {
        if (in_sizes[i] == M_DIM * K_DIM)       x    = (const float*)d_in[i];
        else if (in_sizes[i] == N_DIM)          bias = (const float*)d_in[i];
        else                                    W32  = (const int*)d_in[i];
    }
    float* out = (float*)d_out;

    absmax_part_kernel<<<2048, 256>>>(x);
    absmax_reduce_kernel<<<1, 1024>>>();
    quant_convert_kernel<<<(unsigned)(NW4 / 256), 256>>>(x, W32);

    cudaFuncSetAttribute(gemm_kernel, cudaFuncAttributeMaxDynamicSharedMemorySize,
                         (int)SMEM_TOTAL);
    gemm_kernel<<<dim3(N_DIM / 256, M_DIM / 128), 256, SMEM_TOTAL>>>(bias, out);
}

// round 16
// speedup vs baseline: 2.7947x; 1.0671x over previous
#include <cuda_runtime.h>
#include <cuda_bf16.h>
#include <cstdint>

// ---------------------------------------------------------------------------
// y = (xq @ W) * (x_scale*Y_SCALE) + bias
//   x: [2048,4096] f32, W: [4096,11008] int32 (promoted int8), bias f32.
// GEMM: legacy HMMA mma.m16n8k16.f32.bf16 (rt~8/SMSP).
// R12: chunk-128 + interleaved loads -> tensor 63.7%. Residual ~2000 cyc/chunk
// = completion latency of LATE-committed prefetch batches. R13: front-load all
// 8 batches into ki=0..3 and commit at ki=3 -> ~2048 cyc of slack before the
// next chunk's cp_wait<0>.
// ---------------------------------------------------------------------------
#define M_DIM 2048
#define K_DIM 4096
#define N_DIM 11008
#define Y_SCALE 0.0123f

__device__ __nv_bfloat16 g_xa[(size_t)M_DIM * K_DIM];   // 16 MB bf16 acts
__device__ __nv_bfloat16 g_Wb[(size_t)K_DIM * N_DIM];   // 90 MB bf16 W [K,N]
__device__ float g_part[2048];
__device__ float g_absmax;

// ---------------------------------------------------------------------------
// PTX helpers
// ---------------------------------------------------------------------------
static __device__ __forceinline__ uint32_t smem_u32(const void* p) {
    return (uint32_t)__cvta_generic_to_shared(p);
}
static __device__ __forceinline__ void cp_async16(uint32_t smem_addr, const void* gptr) {
    asm volatile("cp.async.cg.shared.global [%0], [%1], 16;"
                 :: "r"(smem_addr), "l"(gptr) : "memory");
}
static __device__ __forceinline__ void cp_commit() {
    asm volatile("cp.async.commit_group;" ::: "memory");
}
template <int N>
static __device__ __forceinline__ void cp_wait() {
    asm volatile("cp.async.wait_group %0;" :: "n"(N) : "memory");
}
static __device__ __forceinline__ void ldsm_x4(int& r0, int& r1, int& r2, int& r3,
                                               uint32_t addr) {
    asm volatile("ldmatrix.sync.aligned.m8n8.x4.shared.b16 {%0,%1,%2,%3}, [%4];"
                 : "=r"(r0), "=r"(r1), "=r"(r2), "=r"(r3) : "r"(addr));
}
static __device__ __forceinline__ void ldsm_x2t(int& r0, int& r1, uint32_t addr) {
    asm volatile("ldmatrix.sync.aligned.m8n8.x2.trans.shared.b16 {%0,%1}, [%2];"
                 : "=r"(r0), "=r"(r1) : "r"(addr));
}
static __device__ __forceinline__ void mma_bf16(
    float& c0, float& c1, float& c2, float& c3,
    int a0, int a1, int a2, int a3, int b0, int b1)
{
    asm volatile(
        "mma.sync.aligned.m16n8k16.row.col.f32.bf16.bf16.f32 "
        "{%0,%1,%2,%3}, {%4,%5,%6,%7}, {%8,%9}, {%0,%1,%2,%3};"
        : "+f"(c0), "+f"(c1), "+f"(c2), "+f"(c3)
        : "r"(a0), "r"(a1), "r"(a2), "r"(a3), "r"(b0), "r"(b1));
}
static __device__ __forceinline__ uint32_t bf16bits(__nv_bfloat16 h) {
    return (uint32_t)__bfloat16_as_ushort(h);
}

// ---------------------------------------------------------------------------
// Kernel 1: per-block |x| max -> g_part[2048]
// ---------------------------------------------------------------------------
__global__ void absmax_part_kernel(const float* __restrict__ x) {
    const float4* x4 = reinterpret_cast<const float4*>(x);
    const int n4 = (M_DIM * K_DIM) / 4;
    int tid = blockIdx.x * blockDim.x + threadIdx.x;
    int stride = gridDim.x * blockDim.x;
    float m = 0.0f;
    for (int i = tid; i < n4; i += stride) {
        float4 v = x4[i];
        m = fmaxf(m, fmaxf(fmaxf(fabsf(v.x), fabsf(v.y)), fmaxf(fabsf(v.z), fabsf(v.w))));
    }
    #pragma unroll
    for (int o = 16; o > 0; o >>= 1) m = fmaxf(m, __shfl_xor_sync(0xFFFFFFFFu, m, o));
    __shared__ float wmax[8];
    if ((threadIdx.x & 31) == 0) wmax[threadIdx.x >> 5] = m;
    __syncthreads();
    if (threadIdx.x < 32) {
        float mm = (threadIdx.x < 8) ? wmax[threadIdx.x] : 0.0f;
        #pragma unroll
        for (int o = 4; o > 0; o >>= 1) mm = fmaxf(mm, __shfl_xor_sync(0xFFFFFFFFu, mm, o));
        if (threadIdx.x == 0) g_part[blockIdx.x] = mm;
    }
}

// ---------------------------------------------------------------------------
// Kernel 2: reduce partials -> g_absmax
// ---------------------------------------------------------------------------
__global__ void absmax_reduce_kernel() {
    __shared__ float sm[32];
    int t = threadIdx.x;                         // 1024 threads
    float m = fmaxf(g_part[t], g_part[t + 1024]);
    #pragma unroll
    for (int o = 16; o > 0; o >>= 1) m = fmaxf(m, __shfl_xor_sync(0xFFFFFFFFu, m, o));
    if ((t & 31) == 0) sm[t >> 5] = m;
    __syncthreads();
    if (t < 32) {
        float mm = sm[t];
        #pragma unroll
        for (int o = 16; o > 0; o >>= 1) mm = fmaxf(mm, __shfl_xor_sync(0xFFFFFFFFu, mm, o));
        if (t == 0) g_absmax = mm;
    }
}

// ---------------------------------------------------------------------------
// Kernel 3 (fused): quantize x -> bf16; convert W int32 -> bf16.
// ---------------------------------------------------------------------------
#define NX4 (M_DIM * K_DIM / 4)
#define NW4 ((size_t)K_DIM * N_DIM / 4)
__global__ void quant_convert_kernel(const float* __restrict__ x,
                                     const int* __restrict__ W32) {
    size_t i = (size_t)blockIdx.x * blockDim.x + threadIdx.x;
    int4 w = *reinterpret_cast<const int4*>(W32 + 4 * i);
    uint32_t w0 = bf16bits(__float2bfloat16_rn((float)w.x)) |
                  (bf16bits(__float2bfloat16_rn((float)w.y)) << 16);
    uint32_t w1 = bf16bits(__float2bfloat16_rn((float)w.z)) |
                  (bf16bits(__float2bfloat16_rn((float)w.w)) << 16);
    uint2 wp; wp.x = w0; wp.y = w1;
    reinterpret_cast<uint2*>(g_Wb)[i] = wp;
    if (i < NX4) {
        float xs = g_absmax * (1.0f / 128.0f);
        float4 v = reinterpret_cast<const float4*>(x)[i];
        float a = fminf(fmaxf(rintf(v.x / xs), -128.0f), 127.0f);
        float b = fminf(fmaxf(rintf(v.y / xs), -128.0f), 127.0f);
        float c = fminf(fmaxf(rintf(v.z / xs), -128.0f), 127.0f);
        float d = fminf(fmaxf(rintf(v.w / xs), -128.0f), 127.0f);
        uint32_t lo = bf16bits(__float2bfloat16_rn(a)) | (bf16bits(__float2bfloat16_rn(b)) << 16);
        uint32_t hi = bf16bits(__float2bfloat16_rn(c)) | (bf16bits(__float2bfloat16_rn(d)) << 16);
        uint2 pk; pk.x = lo; pk.y = hi;
        reinterpret_cast<uint2*>(g_xa)[i] = pk;
    }
}

// ---------------------------------------------------------------------------
// Kernel 4: bf16 HMMA GEMM. CTA 128x256, 8 warps (2x4, warp 64x64).
// K chunk = 128 elements, 2 stages. All 8 prefetch batches issued during
// ki=0..3 (2/step), committed at ki=3 -> ~2048 cyc completion slack.
// PITCH_A=272, PITCH_B=528 (16B-group === 1 mod 8 -> conflict-free ldmatrix).
// ---------------------------------------------------------------------------
static constexpr int CHUNK_K = 128;
static constexpr int PITCH_A = 272;                     // 256B data + 16B pad
static constexpr int PITCH_B = 528;                     // 512B data + 16B pad
static constexpr uint32_t A_SZ = 128 * PITCH_A;         // 34816
static constexpr uint32_t B_SZ = 128 * PITCH_B;         // 67584
static constexpr uint32_t STAGE = A_SZ + B_SZ;          // 102400
static constexpr uint32_t SMEM_TOTAL = 2 * STAGE;       // 204800

// one batch = 1 A seg + 2 B segs per thread; 8 batches cover the whole chunk
static __device__ __forceinline__ void load_batch(uint32_t stage_base, int chunk,
                                                  int m0, int n0, int tid, int i) {
    const int k0 = chunk * CHUNK_K;
    // A: 128 rows x 16 segs of 16B = 2048 segs; batch i -> seg f = tid + 256*i
    {
        int f = tid + 256 * i;
        int row = f >> 4, seg = f & 15;
        cp_async16(stage_base + (uint32_t)(row * PITCH_A + seg * 16),
                   g_xa + (size_t)(m0 + row) * K_DIM + k0 + seg * 8);
    }
    // B: 128 rows x 32 segs of 16B = 4096 segs; batch i -> segs 2i, 2i+1
    #pragma unroll
    for (int jj = 0; jj < 2; jj++) {
        int f = tid + 256 * (2 * i + jj);
        int row = f >> 5, seg = f & 31;
        cp_async16(stage_base + A_SZ + (uint32_t)(row * PITCH_B + seg * 16),
                   g_Wb + (size_t)(k0 + row) * N_DIM + n0 + seg * 8);
    }
}

__global__ __launch_bounds__(256, 1) void gemm_kernel(const float* __restrict__ bias,
                                                      float* __restrict__ out) {
    extern __shared__ char smem[];
    const uint32_t sb = smem_u32(smem);
    const int tid = threadIdx.x;
    const int wid = tid >> 5;
    const int lid = tid & 31;
    const int g = lid >> 2;
    const int q = lid & 3;
    const int warp_row = (wid >> 2) * 64;   // 0 or 64
    const int warp_col = (wid & 3) * 64;    // 0,64,128,192
    const int m0 = blockIdx.y * 128;
    const int n0 = blockIdx.x * 256;

    const uint32_t aoff = (uint32_t)((lid & 15) * PITCH_A + (lid >> 4) * 16);
    const uint32_t brow = (uint32_t)((lid & 15) * PITCH_B);

    float acc[4][8][4];
    #pragma unroll
    for (int t = 0; t < 4; t++)
        #pragma unroll
        for (int u = 0; u < 8; u++)
            #pragma unroll
            for (int r = 0; r < 4; r++) acc[t][u][r] = 0.0f;

    const int KCHUNKS = K_DIM / CHUNK_K;   // 32

    // prologue: chunk 0 -> stage 0
    #pragma unroll
    for (int i = 0; i < 8; i++) load_batch(sb, 0, m0, n0, tid, i);
    cp_commit();

    for (int c = 0; c < KCHUNKS; c++) {
        const int s = c & 1;
        cp_wait<0>();            // stage s data resident
        __syncthreads();         // publish + fence stage s^1 reads from iter c-1

        const uint32_t sA = sb + (uint32_t)s * STAGE;
        const uint32_t sB = sA + A_SZ;
        const uint32_t nbase = sb + (uint32_t)(s ^ 1) * STAGE;
        const int nc = c + 1;
        const int ncw = (nc < KCHUNKS) ? nc : 0;   // wrap tail (harmless dummy)

        #pragma unroll
        for (int ki = 0; ki < 8; ki++) {           // 8 k16 steps
            const int kk = ki * 16;
            int a[4][4], bb[8][2];
            #pragma unroll
            for (int t = 0; t < 4; t++)
                ldsm_x4(a[t][0], a[t][1], a[t][2], a[t][3],
                        sA + (uint32_t)((warp_row + t * 16) * PITCH_A + kk * 2) + aoff);
            #pragma unroll
            for (int u = 0; u < 8; u++)
                ldsm_x2t(bb[u][0], bb[u][1],
                         sB + (uint32_t)(kk * PITCH_B + (warp_col + u * 8) * 2) + brow);
            // front-loaded prefetch: all 8 batches during ki=0..3, commit at 3
            if (ki < 4) {
                load_batch(nbase, ncw, m0, n0, tid, 2 * ki);
                load_batch(nbase, ncw, m0, n0, tid, 2 * ki + 1);
                if (ki == 3) cp_commit();
            }
            #pragma unroll
            for (int u = 0; u < 8; u++)
                #pragma unroll
                for (int t = 0; t < 4; t++)
                    mma_bf16(acc[t][u][0], acc[t][u][1], acc[t][u][2], acc[t][u][3],
                             a[t][0], a[t][1], a[t][2], a[t][3], bb[u][0], bb[u][1]);
        }
    }

    // epilogue: y = c * alpha + bias
    const float alpha = g_absmax * (1.0f / 128.0f) * Y_SCALE;
    #pragma unroll
    for (int t = 0; t < 4; t++) {
        const int r0 = m0 + warp_row + t * 16 + g;
        #pragma unroll
        for (int u = 0; u < 8; u++) {
            const int col = n0 + warp_col + u * 8 + q * 2;
            const float2 bv = *reinterpret_cast<const float2*>(bias + col);
            float2 o0, o1;
            o0.x = acc[t][u][0] * alpha + bv.x;
            o0.y = acc[t][u][1] * alpha + bv.y;
            o1.x = acc[t][u][2] * alpha + bv.x;
            o1.y = acc[t][u][3] * alpha + bv.y;
            *reinterpret_cast<float2*>(out + (size_t)r0 * N_DIM + col) = o0;
            *reinterpret_cast<float2*>(out + (size_t)(r0 + 8) * N_DIM + col) = o1;
        }
    }
}

// ---------------------------------------------------------------------------
// Launcher — inputs identified by element count:
//   x: 8388608 f32 | W: 45088768 int32 | bias: 11008 f32
// ---------------------------------------------------------------------------
extern "C" void kernel_launch(void* const* d_in, const int* in_sizes, int n_in,
                              void* d_out, int out_size) {
    (void)out_size;
    const float* x    = nullptr;
    const int*   W32  = nullptr;
    const float* bias = nullptr;
    for (int i = 0; i < n_in; i++) {
        if (in_sizes[i] == M_DIM * K_DIM)       x    = (const float*)d_in[i];
        else if (in_sizes[i] == N_DIM)          bias = (const float*)d_in[i];
        else                                    W32  = (const int*)d_in[i];
    }
    float* out = (float*)d_out;

    absmax_part_kernel<<<2048, 256>>>(x);
    absmax_reduce_kernel<<<1, 1024>>>();
    quant_convert_kernel<<<(unsigned)(NW4 / 256), 256>>>(x, W32);

    cudaFuncSetAttribute(gemm_kernel, cudaFuncAttributeMaxDynamicSharedMemorySize,
                         (int)SMEM_TOTAL);
    gemm_kernel<<<dim3(N_DIM / 256, M_DIM / 128), 256, SMEM_TOTAL>>>(bias, out);
}